// round 16
// baseline (speedup 1.0000x reference)
#include <cuda_runtime.h>
#include <cuda_bf16.h>
#include <math.h>

// Problem constants
#define DD   1024
#define NH   16
#define HDIM 64
#define BB   2
#define NQ   1024
#define NC   4096
#define MQ   (BB*NQ)   // 2048 query rows
#define MC   (BB*NC)   // 8192 context rows
#define NSPLIT 2
#define NCSP (NC / NSPLIT)   // 2048 keys per split

// Scratch (static device globals: allocation-free)
__device__ float         g_qn  [(size_t)MQ*DD];   // fp32 qn (residual)
__device__ __nv_bfloat16 g_qnh [(size_t)MQ*DD];
__device__ __nv_bfloat16 g_cnh [(size_t)MC*DD];
__device__ __nv_bfloat16 g_Qp  [(size_t)MQ*DD];
__device__ __nv_bfloat16 g_Kp  [(size_t)MC*DD];
__device__ __nv_bfloat16 g_Vp  [(size_t)MC*DD];
__device__ __nv_bfloat16 g_AO  [(size_t)MQ*DD];
__device__ __nv_bfloat16 g_wqh [(size_t)DD*DD];
__device__ __nv_bfloat16 g_wkvh[(size_t)2*DD*DD]; // concat [wk; wv]
__device__ __nv_bfloat16 g_woh [(size_t)DD*DD];
__device__ float         g_Op  [(size_t)NSPLIT*MQ*DD];   // unnormalized partial O
__device__ float2        g_ml  [(size_t)NSPLIT*MQ*NH];   // per-row (m, l) partials

// ---------------------------------------------------------------------------
// PTX helpers
// ---------------------------------------------------------------------------
__device__ __forceinline__ void mma_bf16(float* c, const unsigned* a,
                                         unsigned b0, unsigned b1) {
    asm volatile(
        "mma.sync.aligned.m16n8k16.row.col.f32.bf16.bf16.f32 "
        "{%0,%1,%2,%3}, {%4,%5,%6,%7}, {%8,%9}, {%0,%1,%2,%3};"
        : "+f"(c[0]), "+f"(c[1]), "+f"(c[2]), "+f"(c[3])
        : "r"(a[0]), "r"(a[1]), "r"(a[2]), "r"(a[3]), "r"(b0), "r"(b1));
}

__device__ __forceinline__ void ldsm_x4(unsigned& r0, unsigned& r1,
                                        unsigned& r2, unsigned& r3, unsigned addr) {
    asm volatile("ldmatrix.sync.aligned.m8n8.x4.shared.b16 {%0,%1,%2,%3}, [%4];"
                 : "=r"(r0), "=r"(r1), "=r"(r2), "=r"(r3) : "r"(addr));
}

__device__ __forceinline__ void ldsm_x4_trans(unsigned& r0, unsigned& r1,
                                              unsigned& r2, unsigned& r3, unsigned addr) {
    asm volatile("ldmatrix.sync.aligned.m8n8.x4.trans.shared.b16 {%0,%1,%2,%3}, [%4];"
                 : "=r"(r0), "=r"(r1), "=r"(r2), "=r"(r3) : "r"(addr));
}

__device__ __forceinline__ void cp_async16(unsigned dst, const void* src) {
    asm volatile("cp.async.cg.shared.global [%0], [%1], 16;" :: "r"(dst), "l"(src));
}
__device__ __forceinline__ void cp_commit() {
    asm volatile("cp.async.commit_group;");
}
template <int N>
__device__ __forceinline__ void cp_wait() {
    asm volatile("cp.async.wait_group %0;" :: "n"(N));
}

// pack two fp32 into bf16x2 register (lo, hi)
__device__ __forceinline__ unsigned pack_bf16x2(float lo, float hi) {
    __nv_bfloat162 h = __floats2bfloat162_rn(lo, hi);
    return *reinterpret_cast<unsigned*>(&h);
}

// ---------------------------------------------------------------------------
// Fused warp-per-row LayerNorm + weight convert.
// ---------------------------------------------------------------------------
#define LN_BLOCKS ((MQ + MC) / 8)   // 1280

__global__ void __launch_bounds__(256) ln_cvt_kernel(
    const float* __restrict__ query, const float* __restrict__ context,
    const float* __restrict__ gq, const float* __restrict__ bq,
    const float* __restrict__ gkv, const float* __restrict__ bkv,
    float* __restrict__ qn, __nv_bfloat16* __restrict__ qnh,
    __nv_bfloat16* __restrict__ cnh,
    const float* __restrict__ wq, const float* __restrict__ wk,
    const float* __restrict__ wv, const float* __restrict__ wo,
    __nv_bfloat16* __restrict__ wqh, __nv_bfloat16* __restrict__ wkvh,
    __nv_bfloat16* __restrict__ woh)
{
    const int bid = blockIdx.x;
    const int t = threadIdx.x;

    if (bid >= LN_BLOCKS) {
        const int idx = bid - LN_BLOCKS;
        const int m = idx >> 10;
        const int i = ((idx & 1023) * 256 + t) * 4;
        const float* s;
        __nv_bfloat16* d;
        if      (m == 0) { s = wq; d = wqh; }
        else if (m == 1) { s = wk; d = wkvh; }
        else if (m == 2) { s = wv; d = wkvh + (size_t)DD * DD; }
        else             { s = wo; d = woh; }
        const float4 v = *reinterpret_cast<const float4*>(s + i);
        __nv_bfloat162* o = reinterpret_cast<__nv_bfloat162*>(d + i);
        o[0] = __floats2bfloat162_rn(v.x, v.y);
        o[1] = __floats2bfloat162_rn(v.z, v.w);
        return;
    }

    const int w    = t >> 5;
    const int lane = t & 31;
    const int grow = bid * 8 + w;
    const bool isq = (grow < MQ);
    const int row  = isq ? grow : grow - MQ;

    const float* x = isq ? (query + (size_t)row * DD) : (context + (size_t)row * DD);
    const float* gamma = isq ? gq : gkv;
    const float* beta  = isq ? bq : bkv;
    __nv_bfloat16* yh  = isq ? (qnh + (size_t)row * DD) : (cnh + (size_t)row * DD);

    float4 v[8];
    #pragma unroll
    for (int i = 0; i < 8; i++)
        v[i] = *reinterpret_cast<const float4*>(x + i * 128 + lane * 4);

    float s = 0.f, ss = 0.f;
    #pragma unroll
    for (int i = 0; i < 8; i++) {
        s  += v[i].x + v[i].y + v[i].z + v[i].w;
        ss += v[i].x * v[i].x + v[i].y * v[i].y + v[i].z * v[i].z + v[i].w * v[i].w;
    }
    #pragma unroll
    for (int o = 16; o > 0; o >>= 1) {
        s  += __shfl_xor_sync(0xffffffffu, s,  o);
        ss += __shfl_xor_sync(0xffffffffu, ss, o);
    }

    const float mu  = s * (1.f / DD);
    const float var = ss * (1.f / DD) - mu * mu;
    const float inv = rsqrtf(var + 1e-5f);

    #pragma unroll
    for (int i = 0; i < 8; i++) {
        const int col = i * 128 + lane * 4;
        const float4 g = *reinterpret_cast<const float4*>(gamma + col);
        const float4 b = *reinterpret_cast<const float4*>(beta + col);
        float4 o;
        o.x = (v[i].x - mu) * inv * g.x + b.x;
        o.y = (v[i].y - mu) * inv * g.y + b.y;
        o.z = (v[i].z - mu) * inv * g.z + b.z;
        o.w = (v[i].w - mu) * inv * g.w + b.w;
        if (isq) *reinterpret_cast<float4*>(qn + (size_t)row * DD + col) = o;
        __nv_bfloat162* oh = reinterpret_cast<__nv_bfloat162*>(yh + col);
        oh[0] = __floats2bfloat162_rn(o.x, o.y);
        oh[1] = __floats2bfloat162_rn(o.z, o.w);
    }
}

// ---------------------------------------------------------------------------
// GEMM mainloop core (round-8 proven): 128x128x32 tile, 4-stage cp.async.
// ---------------------------------------------------------------------------
#define RS 40
#define GTILE (128 * RS)
#define GSTAGES 4
#define GEMM_SMEM (2 * GSTAGES * GTILE * 2)   // 81920 bytes

struct GemmCtx {
    const __nv_bfloat16 *A, *W;
    int m0, n0;
};

__device__ __forceinline__ void gemm_mainloop(
    const GemmCtx& cx, __nv_bfloat16* gsm, float acc[2][8][4])
{
    __nv_bfloat16* As = gsm;
    __nv_bfloat16* Bs = gsm + GSTAGES * GTILE;
    const int t    = threadIdx.x;
    const int lane = t & 31;
    const int w    = t >> 5;
    const int wm   = w >> 1;
    const int wn   = w & 1;

    const unsigned as_base = (unsigned)__cvta_generic_to_shared(As);
    const unsigned bs_base = (unsigned)__cvta_generic_to_shared(Bs);

    const int arow_in  = (lane & 7) + ((lane >> 3) & 1) * 8;
    const int akoff_in = (lane >> 4) * 8;
    const int brow_in  = (lane & 7) + (lane >> 4) * 8;
    const int bkoff_in = ((lane >> 3) & 1) * 8;

    const int srow = t >> 1;
    const int sc   = (t & 1) * 16;

    const __nv_bfloat16* Ap = cx.A + (size_t)(cx.m0 + srow) * DD + sc;
    const __nv_bfloat16* Wp = cx.W + (size_t)(cx.n0 + srow) * DD + sc;
    const unsigned a_dst = as_base + (srow * RS + sc) * 2;
    const unsigned b_dst = bs_base + (srow * RS + sc) * 2;

    const int NK = DD / 32;

    #pragma unroll
    for (int st = 0; st < GSTAGES - 1; st++) {
        cp_async16(a_dst + st * GTILE * 2,      Ap + st * 32);
        cp_async16(a_dst + st * GTILE * 2 + 16, Ap + st * 32 + 8);
        cp_async16(b_dst + st * GTILE * 2,      Wp + st * 32);
        cp_async16(b_dst + st * GTILE * 2 + 16, Wp + st * 32 + 8);
        cp_commit();
    }

    #pragma unroll
    for (int mf = 0; mf < 2; mf++)
        #pragma unroll
        for (int nf = 0; nf < 8; nf++)
            #pragma unroll
            for (int i = 0; i < 4; i++) acc[mf][nf][i] = 0.f;

    int cur = 0, nxt = GSTAGES - 1;
    for (int it = 0; it < NK; it++) {
        if (it + 2 < NK)      cp_wait<2>();
        else if (it + 1 < NK) cp_wait<1>();
        else                  cp_wait<0>();
        __syncthreads();

        if (it + GSTAGES - 1 < NK) {
            const int ko = (it + GSTAGES - 1) * 32;
            cp_async16(a_dst + nxt * GTILE * 2,      Ap + ko);
            cp_async16(a_dst + nxt * GTILE * 2 + 16, Ap + ko + 8);
            cp_async16(b_dst + nxt * GTILE * 2,      Wp + ko);
            cp_async16(b_dst + nxt * GTILE * 2 + 16, Wp + ko + 8);
            cp_commit();
        }

        const unsigned as_st = as_base + cur * GTILE * 2;
        const unsigned bs_st = bs_base + cur * GTILE * 2;

        #pragma unroll
        for (int ks = 0; ks < 2; ks++) {
            unsigned a[2][4];
            #pragma unroll
            for (int mf = 0; mf < 2; mf++) {
                const int r  = wm * 32 + mf * 16 + arow_in;
                const int ko = ks * 16 + akoff_in;
                ldsm_x4(a[mf][0], a[mf][1], a[mf][2], a[mf][3],
                        as_st + (r * RS + ko) * 2);
            }
            unsigned bf[4][4];
            #pragma unroll
            for (int ng = 0; ng < 4; ng++) {
                const int nr = wn * 64 + ng * 16 + brow_in;
                const int ko = ks * 16 + bkoff_in;
                ldsm_x4(bf[ng][0], bf[ng][1], bf[ng][2], bf[ng][3],
                        bs_st + (nr * RS + ko) * 2);
            }
            #pragma unroll
            for (int ng = 0; ng < 4; ng++) {
                mma_bf16(acc[0][2*ng+0], a[0], bf[ng][0], bf[ng][1]);
                mma_bf16(acc[1][2*ng+0], a[1], bf[ng][0], bf[ng][1]);
                mma_bf16(acc[0][2*ng+1], a[0], bf[ng][2], bf[ng][3]);
                mma_bf16(acc[1][2*ng+1], a[1], bf[ng][2], bf[ng][3]);
            }
        }

        cur = (cur + 1) & (GSTAGES - 1);
        nxt = (nxt + 1) & (GSTAGES - 1);
    }
}

// ---------------------------------------------------------------------------
// Fused Q + KV projection: grid = 1024 KV CTAs then 128 Q CTAs.
// ---------------------------------------------------------------------------
__global__ void __launch_bounds__(256) proj_fused_kernel(
    const __nv_bfloat16* __restrict__ qnh, const __nv_bfloat16* __restrict__ cnh,
    const __nv_bfloat16* __restrict__ wqh, const __nv_bfloat16* __restrict__ wkvh,
    const float* __restrict__ bq, const float* __restrict__ bk,
    const float* __restrict__ bv,
    __nv_bfloat16* __restrict__ Qp, __nv_bfloat16* __restrict__ Kp,
    __nv_bfloat16* __restrict__ Vp)
{
    extern __shared__ __align__(16) __nv_bfloat16 gsm[];

    GemmCtx cx;
    const float* bias;
    __nv_bfloat16* Co;
    int nbase;
    const int bid = blockIdx.x;
    if (bid < 1024) {
        cx.A = cnh; cx.W = wkvh;
        cx.m0 = (bid >> 4) * 128;
        cx.n0 = (bid & 15) * 128;
        if (cx.n0 < DD) { bias = bk; Co = Kp; nbase = cx.n0; }
        else            { bias = bv; Co = Vp; nbase = cx.n0 - DD; }
    } else {
        const int i2 = bid - 1024;
        cx.A = qnh; cx.W = wqh;
        cx.m0 = (i2 >> 3) * 128;
        cx.n0 = (i2 & 7) * 128;
        bias = bq; Co = Qp; nbase = cx.n0;
    }

    float acc[2][8][4];
    gemm_mainloop(cx, gsm, acc);

    const int t = threadIdx.x, lane = t & 31, w = t >> 5;
    const int wm = w >> 1, wn = w & 1, g = lane >> 2, tg = lane & 3;

    #pragma unroll
    for (int mf = 0; mf < 2; mf++) {
        #pragma unroll
        for (int nf = 0; nf < 8; nf++) {
            const int col = nbase + wn * 64 + nf * 8 + tg * 2;
            const float bx = bias[col], by = bias[col + 1];
            #pragma unroll
            for (int half = 0; half < 2; half++) {
                const size_t grow = (size_t)(cx.m0 + wm * 32 + mf * 16 + g + half * 8);
                *reinterpret_cast<__nv_bfloat162*>(Co + grow * DD + col) =
                    __floats2bfloat162_rn(acc[mf][nf][half * 2 + 0] + bx,
                                          acc[mf][nf][half * 2 + 1] + by);
            }
        }
    }
}

// ---------------------------------------------------------------------------
// O projection + bias + residual (fp32 out)
// ---------------------------------------------------------------------------
__global__ void __launch_bounds__(256) oproj_kernel(
    const __nv_bfloat16* __restrict__ A, const __nv_bfloat16* __restrict__ W,
    const float* __restrict__ bias, const float* __restrict__ R,
    float* __restrict__ Cf)
{
    extern __shared__ __align__(16) __nv_bfloat16 gsm[];

    GemmCtx cx;
    cx.A = A; cx.W = W;
    cx.m0 = blockIdx.y * 128;
    cx.n0 = blockIdx.x * 128;

    float acc[2][8][4];
    gemm_mainloop(cx, gsm, acc);

    const int t = threadIdx.x, lane = t & 31, w = t >> 5;
    const int wm = w >> 1, wn = w & 1, g = lane >> 2, tg = lane & 3;

    #pragma unroll
    for (int mf = 0; mf < 2; mf++) {
        #pragma unroll
        for (int nf = 0; nf < 8; nf++) {
            const int col = cx.n0 + wn * 64 + nf * 8 + tg * 2;
            const float bx = bias[col], by = bias[col + 1];
            #pragma unroll
            for (int half = 0; half < 2; half++) {
                const size_t grow = (size_t)(cx.m0 + wm * 32 + mf * 16 + g + half * 8);
                const float2 rv = *reinterpret_cast<const float2*>(R + grow * DD + col);
                float2 o;
                o.x = acc[mf][nf][half * 2 + 0] + bx + rv.x;
                o.y = acc[mf][nf][half * 2 + 1] + by + rv.y;
                *reinterpret_cast<float2*>(Cf + grow * DD + col) = o;
            }
        }
    }
}

// ---------------------------------------------------------------------------
// Split-KV BF16 flash attention: grid (8, 16, 4); z = b*2 + split.
// Each CTA processes NCSP=2048 keys; writes UNNORMALIZED fp32 partials + (m,l).
// 128 threads = 4 warps, warp tile m32xn64, 1 wf/MMA on K/V; Q frags reloaded
// per tile (register diet for 3 CTAs/SM). Skip-rescale kept (exact).
// ---------------------------------------------------------------------------
#define QSTR 72
#define OFF_Q 0
#define OFF_K (128 * QSTR)
#define OFF_V (OFF_K + 2 * 64 * QSTR)
#define SM_ELEMS (OFF_V + 2 * 64 * QSTR)
#define KVBUF (64 * QSTR)
#define SSCALE 0.18033688f   /* 0.125 * log2(e) */

__global__ void __launch_bounds__(128, 3) attn_split_kernel(
    const __nv_bfloat16* __restrict__ Q, const __nv_bfloat16* __restrict__ K,
    const __nv_bfloat16* __restrict__ V, float* __restrict__ Op,
    float2* __restrict__ ml)
{
    extern __shared__ __align__(16) __nv_bfloat16 smem[];
    const unsigned sm_base = (unsigned)__cvta_generic_to_shared(smem);

    const int z  = blockIdx.z;
    const int b  = z >> 1;
    const int sp = z & 1;
    const int h  = blockIdx.y;
    const int q0 = blockIdx.x * 128;
    const int t  = threadIdx.x;
    const int w  = t >> 5;
    const int lane = t & 31;
    const int g  = lane >> 2;
    const int tg = lane & 3;
    const int wrow = w * 32;

    const int arow_in  = (lane & 7) + ((lane >> 3) & 1) * 8;
    const int akoff_in = (lane >> 4) * 8;
    const int brow_in  = (lane & 7) + (lane >> 4) * 8;
    const int bkoff_in = ((lane >> 3) & 1) * 8;

    const __nv_bfloat16* Qb = Q + ((size_t)(b * NQ + q0)) * DD + h * HDIM;
    const __nv_bfloat16* Kb = K + ((size_t)(b * NC + sp * NCSP)) * DD + h * HDIM;
    const __nv_bfloat16* Vb = V + ((size_t)(b * NC + sp * NCSP)) * DD + h * HDIM;

    // Prologue: Q + K/V tile 0
    #pragma unroll
    for (int i = t; i < 128 * 8; i += 128) {
        const int r = i >> 3, c = (i & 7) * 8;
        cp_async16(sm_base + (OFF_Q + r * QSTR + c) * 2, Qb + (size_t)r * DD + c);
    }
    #pragma unroll
    for (int i = t; i < 64 * 8; i += 128) {
        const int r = i >> 3, c = (i & 7) * 8;
        cp_async16(sm_base + (OFF_K + r * QSTR + c) * 2, Kb + (size_t)r * DD + c);
        cp_async16(sm_base + (OFF_V + r * QSTR + c) * 2, Vb + (size_t)r * DD + c);
    }
    cp_commit();

    float m_i[4], l_i[4], of[2][8][4];
    #pragma unroll
    for (int i = 0; i < 4; i++) { m_i[i] = -INFINITY; l_i[i] = 0.f; }
    #pragma unroll
    for (int mf = 0; mf < 2; mf++)
        #pragma unroll
        for (int nf = 0; nf < 8; nf++)
            #pragma unroll
            for (int i = 0; i < 4; i++) of[mf][nf][i] = 0.f;

    const int NT = NCSP / 64;   // 32
    for (int it = 0; it < NT; it++) {
        const int cur = it & 1;
        cp_wait<0>();
        __syncthreads();

        if (it + 1 < NT) {
            const int nxt = cur ^ 1;
            #pragma unroll
            for (int i = t; i < 64 * 8; i += 128) {
                const int r = i >> 3, c = (i & 7) * 8;
                const size_t grow = (size_t)((it + 1) * 64 + r) * DD + c;
                cp_async16(sm_base + (OFF_K + nxt * KVBUF + r * QSTR + c) * 2, Kb + grow);
                cp_async16(sm_base + (OFF_V + nxt * KVBUF + r * QSTR + c) * 2, Vb + grow);
            }
            cp_commit();
        }

        const int kbase = OFF_K + cur * KVBUF;
        const int vbase = OFF_V + cur * KVBUF;

        // ---- S = Q K^T : K frags shared across m-halves; Q frags reloaded
        float sf[2][8][4];
        #pragma unroll
        for (int mf = 0; mf < 2; mf++)
            #pragma unroll
            for (int nf = 0; nf < 8; nf++)
                #pragma unroll
                for (int i = 0; i < 4; i++) sf[mf][nf][i] = 0.f;

        #pragma unroll
        for (int ks = 0; ks < 4; ks++) {
            unsigned qa0[4], qa1[4];
            ldsm_x4(qa0[0], qa0[1], qa0[2], qa0[3],
                    sm_base + (OFF_Q + (wrow + arow_in) * QSTR + ks * 16 + akoff_in) * 2);
            ldsm_x4(qa1[0], qa1[1], qa1[2], qa1[3],
                    sm_base + (OFF_Q + (wrow + 16 + arow_in) * QSTR + ks * 16 + akoff_in) * 2);
            unsigned bf[4][4];
            #pragma unroll
            for (int ng = 0; ng < 4; ng++) {
                ldsm_x4(bf[ng][0], bf[ng][1], bf[ng][2], bf[ng][3],
                        sm_base + (kbase + (ng * 16 + brow_in) * QSTR
                                   + ks * 16 + bkoff_in) * 2);
            }
            #pragma unroll
            for (int ng = 0; ng < 4; ng++) {
                mma_bf16(sf[0][2*ng+0], qa0, bf[ng][0], bf[ng][1]);
                mma_bf16(sf[1][2*ng+0], qa1, bf[ng][0], bf[ng][1]);
                mma_bf16(sf[0][2*ng+1], qa0, bf[ng][2], bf[ng][3]);
                mma_bf16(sf[1][2*ng+1], qa1, bf[ng][2], bf[ng][3]);
            }
        }

        // ---- online softmax per m-half; P packed into A-fragments ----
        unsigned pa[2][4][4];
        #pragma unroll
        for (int mf = 0; mf < 2; mf++) {
            float mx0 = -INFINITY, mx1 = -INFINITY;
            #pragma unroll
            for (int nf = 0; nf < 8; nf++) {
                mx0 = fmaxf(mx0, fmaxf(sf[mf][nf][0], sf[mf][nf][1]));
                mx1 = fmaxf(mx1, fmaxf(sf[mf][nf][2], sf[mf][nf][3]));
            }
            mx0 = fmaxf(mx0, __shfl_xor_sync(0xffffffffu, mx0, 1));
            mx0 = fmaxf(mx0, __shfl_xor_sync(0xffffffffu, mx0, 2));
            mx1 = fmaxf(mx1, __shfl_xor_sync(0xffffffffu, mx1, 1));
            mx1 = fmaxf(mx1, __shfl_xor_sync(0xffffffffu, mx1, 2));

            const float mn0 = fmaxf(m_i[mf * 2 + 0], mx0);
            const float mn1 = fmaxf(m_i[mf * 2 + 1], mx1);
            const float f0 = exp2f((m_i[mf * 2 + 0] - mn0) * SSCALE);
            const float f1 = exp2f((m_i[mf * 2 + 1] - mn1) * SSCALE);
            const float c0 = mn0 * SSCALE;
            const float c1 = mn1 * SSCALE;

            float s0 = 0.f, s1 = 0.f;
            #pragma unroll
            for (int nf = 0; nf < 8; nf++) {
                const float p0 = exp2f(fmaf(sf[mf][nf][0], SSCALE, -c0));
                const float p1 = exp2f(fmaf(sf[mf][nf][1], SSCALE, -c0));
                const float p2 = exp2f(fmaf(sf[mf][nf][2], SSCALE, -c1));
                const float p3 = exp2f(fmaf(sf[mf][nf][3], SSCALE, -c1));
                s0 += p0 + p1;
                s1 += p2 + p3;
                const int ks = nf >> 1, hf = nf & 1;
                pa[mf][ks][hf * 2 + 0] = pack_bf16x2(p0, p1);
                pa[mf][ks][hf * 2 + 1] = pack_bf16x2(p2, p3);
            }
            s0 += __shfl_xor_sync(0xffffffffu, s0, 1);
            s0 += __shfl_xor_sync(0xffffffffu, s0, 2);
            s1 += __shfl_xor_sync(0xffffffffu, s1, 1);
            s1 += __shfl_xor_sync(0xffffffffu, s1, 2);

            l_i[mf * 2 + 0] = l_i[mf * 2 + 0] * f0 + s0;
            l_i[mf * 2 + 1] = l_i[mf * 2 + 1] * f1 + s1;
            m_i[mf * 2 + 0] = mn0;
            m_i[mf * 2 + 1] = mn1;

            const bool resc = !__all_sync(0xffffffffu, (f0 == 1.f) && (f1 == 1.f));
            if (resc) {
                #pragma unroll
                for (int nf = 0; nf < 8; nf++) {
                    of[mf][nf][0] *= f0; of[mf][nf][1] *= f0;
                    of[mf][nf][2] *= f1; of[mf][nf][3] *= f1;
                }
            }
        }

        // ---- O += P V ----
        #pragma unroll
        for (int ks = 0; ks < 4; ks++) {
            unsigned bf[4][4];
            #pragma unroll
            for (int ng = 0; ng < 4; ng++) {
                ldsm_x4_trans(bf[ng][0], bf[ng][1], bf[ng][2], bf[ng][3],
                              sm_base + (vbase + (ks * 16 + arow_in) * QSTR
                                         + ng * 16 + akoff_in) * 2);
            }
            #pragma unroll
            for (int ng = 0; ng < 4; ng++) {
                mma_bf16(of[0][2*ng+0], pa[0][ks], bf[ng][0], bf[ng][1]);
                mma_bf16(of[1][2*ng+0], pa[1][ks], bf[ng][0], bf[ng][1]);
                mma_bf16(of[0][2*ng+1], pa[0][ks], bf[ng][2], bf[ng][3]);
                mma_bf16(of[1][2*ng+1], pa[1][ks], bf[ng][2], bf[ng][3]);
            }
        }
    }

    // Epilogue: write UNNORMALIZED fp32 partials + per-row (m, l)
    float*  Ops = Op + (size_t)sp * MQ * DD;
    float2* mls = ml + (size_t)sp * MQ * NH;
    #pragma unroll
    for (int mf = 0; mf < 2; mf++) {
        const int r0 = wrow + mf * 16 + g;
        if (tg == 0) {
            mls[((size_t)(b * NQ + q0 + r0)) * NH + h] =
                make_float2(m_i[mf * 2 + 0], l_i[mf * 2 + 0]);
            mls[((size_t)(b * NQ + q0 + r0 + 8)) * NH + h] =
                make_float2(m_i[mf * 2 + 1], l_i[mf * 2 + 1]);
        }
        #pragma unroll
        for (int nf = 0; nf < 8; nf++) {
            const int col = h * HDIM + nf * 8 + tg * 2;
            float2 o0; o0.x = of[mf][nf][0]; o0.y = of[mf][nf][1];
            float2 o1; o1.x = of[mf][nf][2]; o1.y = of[mf][nf][3];
            *reinterpret_cast<float2*>(Ops + (size_t)(b * NQ + q0 + r0) * DD + col) = o0;
            *reinterpret_cast<float2*>(Ops + (size_t)(b * NQ + q0 + r0 + 8) * DD + col) = o1;
        }
    }
}

// ---------------------------------------------------------------------------
// Combine kernel: merge the 2 split partials (exact rebase) -> bf16 AO.
// Grid MQ blocks x 256 threads; thread t handles cols 4t..4t+3 of its row.
// ---------------------------------------------------------------------------
__global__ void __launch_bounds__(256) attn_combine_kernel(
    const float* __restrict__ Op, const float2* __restrict__ ml,
    __nv_bfloat16* __restrict__ AO)
{
    const int R = blockIdx.x;
    const int t = threadIdx.x;
    const int col = t * 4;
    const int h = col >> 6;

    const float2 a0 = ml[(size_t)R * NH + h];
    const float2 a1 = ml[(size_t)MQ * NH + (size_t)R * NH + h];
    const float M  = fmaxf(a0.x, a1.x);
    const float w0 = exp2f((a0.x - M) * SSCALE);
    const float w1 = exp2f((a1.x - M) * SSCALE);
    const float inv = 1.f / (w0 * a0.y + w1 * a1.y);

    const float4 x0 = *reinterpret_cast<const float4*>(Op + (size_t)R * DD + col);
    const float4 x1 = *reinterpret_cast<const float4*>(Op + (size_t)MQ * DD + (size_t)R * DD + col);

    const float o0 = (w0 * x0.x + w1 * x1.x) * inv;
    const float o1 = (w0 * x0.y + w1 * x1.y) * inv;
    const float o2 = (w0 * x0.z + w1 * x1.z) * inv;
    const float o3 = (w0 * x0.w + w1 * x1.w) * inv;

    __nv_bfloat162* oh = reinterpret_cast<__nv_bfloat162*>(AO + (size_t)R * DD + col);
    oh[0] = __floats2bfloat162_rn(o0, o1);
    oh[1] = __floats2bfloat162_rn(o2, o3);
}

// ---------------------------------------------------------------------------
// Launcher
// ---------------------------------------------------------------------------
extern "C" void kernel_launch(void* const* d_in, const int* in_sizes, int n_in,
                              void* d_out, int out_size)
{
    const float* query   = (const float*)d_in[0];
    const float* context = (const float*)d_in[1];
    const float* wq = (const float*)d_in[2];
    const float* bq = (const float*)d_in[3];
    const float* wk = (const float*)d_in[4];
    const float* bk = (const float*)d_in[5];
    const float* wv = (const float*)d_in[6];
    const float* bv = (const float*)d_in[7];
    const float* wo = (const float*)d_in[8];
    const float* bo = (const float*)d_in[9];
    const float* g_q  = (const float*)d_in[10];
    const float* b_q  = (const float*)d_in[11];
    const float* g_kv = (const float*)d_in[12];
    const float* b_kv = (const float*)d_in[13];
    float* out = (float*)d_out;

    void *qn_, *qnh_, *cnh_, *qp_, *kp_, *vp_, *ao_, *wqh_, *wkvh_, *woh_, *op_, *ml_;
    cudaGetSymbolAddress(&qn_,   g_qn);
    cudaGetSymbolAddress(&qnh_,  g_qnh);
    cudaGetSymbolAddress(&cnh_,  g_cnh);
    cudaGetSymbolAddress(&qp_,   g_Qp);
    cudaGetSymbolAddress(&kp_,   g_Kp);
    cudaGetSymbolAddress(&vp_,   g_Vp);
    cudaGetSymbolAddress(&ao_,   g_AO);
    cudaGetSymbolAddress(&wqh_,  g_wqh);
    cudaGetSymbolAddress(&wkvh_, g_wkvh);
    cudaGetSymbolAddress(&woh_,  g_woh);
    cudaGetSymbolAddress(&op_,   g_Op);
    cudaGetSymbolAddress(&ml_,   g_ml);
    float* qn = (float*)qn_;
    __nv_bfloat16* qnh  = (__nv_bfloat16*)qnh_;
    __nv_bfloat16* cnh  = (__nv_bfloat16*)cnh_;
    __nv_bfloat16* Qp   = (__nv_bfloat16*)qp_;
    __nv_bfloat16* Kp   = (__nv_bfloat16*)kp_;
    __nv_bfloat16* Vp   = (__nv_bfloat16*)vp_;
    __nv_bfloat16* AO   = (__nv_bfloat16*)ao_;
    __nv_bfloat16* wqh  = (__nv_bfloat16*)wqh_;
    __nv_bfloat16* wkvh = (__nv_bfloat16*)wkvh_;
    __nv_bfloat16* woh  = (__nv_bfloat16*)woh_;
    float* Op  = (float*)op_;
    float2* ml = (float2*)ml_;

    const int attn_smem = SM_ELEMS * 2;      // 55296 bytes
    static int configured = 0;
    if (!configured) {
        cudaFuncSetAttribute(attn_split_kernel,
                             cudaFuncAttributeMaxDynamicSharedMemorySize, attn_smem);
        cudaFuncSetAttribute(proj_fused_kernel,
                             cudaFuncAttributeMaxDynamicSharedMemorySize, GEMM_SMEM);
        cudaFuncSetAttribute(oproj_kernel,
                             cudaFuncAttributeMaxDynamicSharedMemorySize, GEMM_SMEM);
        configured = 1;
    }

    // 1. Warp-per-row LayerNorms + weight convert
    ln_cvt_kernel<<<LN_BLOCKS + 4096, 256>>>(query, context, g_q, b_q, g_kv, b_kv,
                                             qn, qnh, cnh,
                                             wq, wk, wv, wo, wqh, wkvh, woh);

    // 2. Fused Q + KV projections
    proj_fused_kernel<<<1152, 256, GEMM_SMEM>>>(qnh, cnh, wqh, wkvh,
                                                bq, bk, bv, Qp, Kp, Vp);

    // 3. Split-KV flash attention (512 CTAs) + combine
    dim3 ga(NQ / 128, NH, BB * NSPLIT);     // (8, 16, 4)
    attn_split_kernel<<<ga, 128, attn_smem>>>(Qp, Kp, Vp, Op, ml);
    attn_combine_kernel<<<MQ, 256>>>(Op, ml, AO);

    // 4. Output projection + bias + residual(qn), fp32 out
    dim3 go(DD / 128, MQ / 128);            // (8, 16)
    oproj_kernel<<<go, 256, GEMM_SMEM>>>(AO, woh, bo, qn, out);
}

// round 17
// speedup vs baseline: 1.0514x; 1.0514x over previous
#include <cuda_runtime.h>
#include <cuda_bf16.h>
#include <math.h>

// Problem constants
#define DD   1024
#define NH   16
#define HDIM 64
#define BB   2
#define NQ   1024
#define NC   4096
#define MQ   (BB*NQ)   // 2048 query rows
#define MC   (BB*NC)   // 8192 context rows

// Scratch (static device globals: allocation-free)
__device__ float         g_qn  [(size_t)MQ*DD];   // fp32 qn (residual)
__device__ __nv_bfloat16 g_qnh [(size_t)MQ*DD];
__device__ __nv_bfloat16 g_cnh [(size_t)MC*DD];
__device__ __nv_bfloat16 g_Qp  [(size_t)MQ*DD];
__device__ __nv_bfloat16 g_Kp  [(size_t)MC*DD];
__device__ __nv_bfloat16 g_Vp  [(size_t)MC*DD];
__device__ __nv_bfloat16 g_AO  [(size_t)MQ*DD];
__device__ __nv_bfloat16 g_wqh [(size_t)DD*DD];
__device__ __nv_bfloat16 g_wkvh[(size_t)2*DD*DD]; // concat [wk; wv]
__device__ __nv_bfloat16 g_woh [(size_t)DD*DD];
__device__ float         g_Op  [(size_t)2*MQ*DD]; // oproj split-K partials

// ---------------------------------------------------------------------------
// PTX helpers
// ---------------------------------------------------------------------------
__device__ __forceinline__ void mma_bf16(float* c, const unsigned* a,
                                         unsigned b0, unsigned b1) {
    asm volatile(
        "mma.sync.aligned.m16n8k16.row.col.f32.bf16.bf16.f32 "
        "{%0,%1,%2,%3}, {%4,%5,%6,%7}, {%8,%9}, {%0,%1,%2,%3};"
        : "+f"(c[0]), "+f"(c[1]), "+f"(c[2]), "+f"(c[3])
        : "r"(a[0]), "r"(a[1]), "r"(a[2]), "r"(a[3]), "r"(b0), "r"(b1));
}

__device__ __forceinline__ void ldsm_x4(unsigned& r0, unsigned& r1,
                                        unsigned& r2, unsigned& r3, unsigned addr) {
    asm volatile("ldmatrix.sync.aligned.m8n8.x4.shared.b16 {%0,%1,%2,%3}, [%4];"
                 : "=r"(r0), "=r"(r1), "=r"(r2), "=r"(r3) : "r"(addr));
}

__device__ __forceinline__ void ldsm_x4_trans(unsigned& r0, unsigned& r1,
                                              unsigned& r2, unsigned& r3, unsigned addr) {
    asm volatile("ldmatrix.sync.aligned.m8n8.x4.trans.shared.b16 {%0,%1,%2,%3}, [%4];"
                 : "=r"(r0), "=r"(r1), "=r"(r2), "=r"(r3) : "r"(addr));
}

__device__ __forceinline__ void cp_async16(unsigned dst, const void* src) {
    asm volatile("cp.async.cg.shared.global [%0], [%1], 16;" :: "r"(dst), "l"(src));
}
__device__ __forceinline__ void cp_commit() {
    asm volatile("cp.async.commit_group;");
}
template <int N>
__device__ __forceinline__ void cp_wait() {
    asm volatile("cp.async.wait_group %0;" :: "n"(N));
}

// pack two fp32 into bf16x2 register (lo, hi)
__device__ __forceinline__ unsigned pack_bf16x2(float lo, float hi) {
    __nv_bfloat162 h = __floats2bfloat162_rn(lo, hi);
    return *reinterpret_cast<unsigned*>(&h);
}

// ---------------------------------------------------------------------------
// Fused warp-per-row LayerNorm + weight convert.
// ---------------------------------------------------------------------------
#define LN_BLOCKS ((MQ + MC) / 8)   // 1280

__global__ void __launch_bounds__(256) ln_cvt_kernel(
    const float* __restrict__ query, const float* __restrict__ context,
    const float* __restrict__ gq, const float* __restrict__ bq,
    const float* __restrict__ gkv, const float* __restrict__ bkv,
    float* __restrict__ qn, __nv_bfloat16* __restrict__ qnh,
    __nv_bfloat16* __restrict__ cnh,
    const float* __restrict__ wq, const float* __restrict__ wk,
    const float* __restrict__ wv, const float* __restrict__ wo,
    __nv_bfloat16* __restrict__ wqh, __nv_bfloat16* __restrict__ wkvh,
    __nv_bfloat16* __restrict__ woh)
{
    const int bid = blockIdx.x;
    const int t = threadIdx.x;

    if (bid >= LN_BLOCKS) {
        const int idx = bid - LN_BLOCKS;
        const int m = idx >> 10;
        const int i = ((idx & 1023) * 256 + t) * 4;
        const float* s;
        __nv_bfloat16* d;
        if      (m == 0) { s = wq; d = wqh; }
        else if (m == 1) { s = wk; d = wkvh; }
        else if (m == 2) { s = wv; d = wkvh + (size_t)DD * DD; }
        else             { s = wo; d = woh; }
        const float4 v = *reinterpret_cast<const float4*>(s + i);
        __nv_bfloat162* o = reinterpret_cast<__nv_bfloat162*>(d + i);
        o[0] = __floats2bfloat162_rn(v.x, v.y);
        o[1] = __floats2bfloat162_rn(v.z, v.w);
        return;
    }

    const int w    = t >> 5;
    const int lane = t & 31;
    const int grow = bid * 8 + w;
    const bool isq = (grow < MQ);
    const int row  = isq ? grow : grow - MQ;

    const float* x = isq ? (query + (size_t)row * DD) : (context + (size_t)row * DD);
    const float* gamma = isq ? gq : gkv;
    const float* beta  = isq ? bq : bkv;
    __nv_bfloat16* yh  = isq ? (qnh + (size_t)row * DD) : (cnh + (size_t)row * DD);

    float4 v[8];
    #pragma unroll
    for (int i = 0; i < 8; i++)
        v[i] = *reinterpret_cast<const float4*>(x + i * 128 + lane * 4);

    float s = 0.f, ss = 0.f;
    #pragma unroll
    for (int i = 0; i < 8; i++) {
        s  += v[i].x + v[i].y + v[i].z + v[i].w;
        ss += v[i].x * v[i].x + v[i].y * v[i].y + v[i].z * v[i].z + v[i].w * v[i].w;
    }
    #pragma unroll
    for (int o = 16; o > 0; o >>= 1) {
        s  += __shfl_xor_sync(0xffffffffu, s,  o);
        ss += __shfl_xor_sync(0xffffffffu, ss, o);
    }

    const float mu  = s * (1.f / DD);
    const float var = ss * (1.f / DD) - mu * mu;
    const float inv = rsqrtf(var + 1e-5f);

    #pragma unroll
    for (int i = 0; i < 8; i++) {
        const int col = i * 128 + lane * 4;
        const float4 g = *reinterpret_cast<const float4*>(gamma + col);
        const float4 b = *reinterpret_cast<const float4*>(beta + col);
        float4 o;
        o.x = (v[i].x - mu) * inv * g.x + b.x;
        o.y = (v[i].y - mu) * inv * g.y + b.y;
        o.z = (v[i].z - mu) * inv * g.z + b.z;
        o.w = (v[i].w - mu) * inv * g.w + b.w;
        if (isq) *reinterpret_cast<float4*>(qn + (size_t)row * DD + col) = o;
        __nv_bfloat162* oh = reinterpret_cast<__nv_bfloat162*>(yh + col);
        oh[0] = __floats2bfloat162_rn(o.x, o.y);
        oh[1] = __floats2bfloat162_rn(o.z, o.w);
    }
}

// ---------------------------------------------------------------------------
// GEMM mainloop core (round-8 proven): 128x128 tile over [kofs, kofs+nk*32),
// 4-stage cp.async, 256 threads = 8 warps (4m x 2n), warp tile 32x64,
// smem stride 40 bf16.
// ---------------------------------------------------------------------------
#define RS 40
#define GTILE (128 * RS)
#define GSTAGES 4
#define GEMM_SMEM (2 * GSTAGES * GTILE * 2)   // 81920 bytes

struct GemmCtx {
    const __nv_bfloat16 *A, *W;
    int m0, n0;
    int kofs, nk;   // k start (elements) and number of k32 iterations
};

__device__ __forceinline__ void gemm_mainloop(
    const GemmCtx& cx, __nv_bfloat16* gsm, float acc[2][8][4])
{
    __nv_bfloat16* As = gsm;
    __nv_bfloat16* Bs = gsm + GSTAGES * GTILE;
    const int t    = threadIdx.x;
    const int lane = t & 31;
    const int w    = t >> 5;
    const int wm   = w >> 1;
    const int wn   = w & 1;

    const unsigned as_base = (unsigned)__cvta_generic_to_shared(As);
    const unsigned bs_base = (unsigned)__cvta_generic_to_shared(Bs);

    const int arow_in  = (lane & 7) + ((lane >> 3) & 1) * 8;
    const int akoff_in = (lane >> 4) * 8;
    const int brow_in  = (lane & 7) + (lane >> 4) * 8;
    const int bkoff_in = ((lane >> 3) & 1) * 8;

    const int srow = t >> 1;
    const int sc   = (t & 1) * 16;

    const __nv_bfloat16* Ap = cx.A + (size_t)(cx.m0 + srow) * DD + cx.kofs + sc;
    const __nv_bfloat16* Wp = cx.W + (size_t)(cx.n0 + srow) * DD + cx.kofs + sc;
    const unsigned a_dst = as_base + (srow * RS + sc) * 2;
    const unsigned b_dst = bs_base + (srow * RS + sc) * 2;

    const int NK = cx.nk;

    #pragma unroll
    for (int st = 0; st < GSTAGES - 1; st++) {
        cp_async16(a_dst + st * GTILE * 2,      Ap + st * 32);
        cp_async16(a_dst + st * GTILE * 2 + 16, Ap + st * 32 + 8);
        cp_async16(b_dst + st * GTILE * 2,      Wp + st * 32);
        cp_async16(b_dst + st * GTILE * 2 + 16, Wp + st * 32 + 8);
        cp_commit();
    }

    #pragma unroll
    for (int mf = 0; mf < 2; mf++)
        #pragma unroll
        for (int nf = 0; nf < 8; nf++)
            #pragma unroll
            for (int i = 0; i < 4; i++) acc[mf][nf][i] = 0.f;

    int cur = 0, nxt = GSTAGES - 1;
    for (int it = 0; it < NK; it++) {
        if (it + 2 < NK)      cp_wait<2>();
        else if (it + 1 < NK) cp_wait<1>();
        else                  cp_wait<0>();
        __syncthreads();

        if (it + GSTAGES - 1 < NK) {
            const int ko = (it + GSTAGES - 1) * 32;
            cp_async16(a_dst + nxt * GTILE * 2,      Ap + ko);
            cp_async16(a_dst + nxt * GTILE * 2 + 16, Ap + ko + 8);
            cp_async16(b_dst + nxt * GTILE * 2,      Wp + ko);
            cp_async16(b_dst + nxt * GTILE * 2 + 16, Wp + ko + 8);
            cp_commit();
        }

        const unsigned as_st = as_base + cur * GTILE * 2;
        const unsigned bs_st = bs_base + cur * GTILE * 2;

        #pragma unroll
        for (int ks = 0; ks < 2; ks++) {
            unsigned a[2][4];
            #pragma unroll
            for (int mf = 0; mf < 2; mf++) {
                const int r  = wm * 32 + mf * 16 + arow_in;
                const int ko = ks * 16 + akoff_in;
                ldsm_x4(a[mf][0], a[mf][1], a[mf][2], a[mf][3],
                        as_st + (r * RS + ko) * 2);
            }
            unsigned bf[4][4];
            #pragma unroll
            for (int ng = 0; ng < 4; ng++) {
                const int nr = wn * 64 + ng * 16 + brow_in;
                const int ko = ks * 16 + bkoff_in;
                ldsm_x4(bf[ng][0], bf[ng][1], bf[ng][2], bf[ng][3],
                        bs_st + (nr * RS + ko) * 2);
            }
            #pragma unroll
            for (int ng = 0; ng < 4; ng++) {
                mma_bf16(acc[0][2*ng+0], a[0], bf[ng][0], bf[ng][1]);
                mma_bf16(acc[1][2*ng+0], a[1], bf[ng][0], bf[ng][1]);
                mma_bf16(acc[0][2*ng+1], a[0], bf[ng][2], bf[ng][3]);
                mma_bf16(acc[1][2*ng+1], a[1], bf[ng][2], bf[ng][3]);
            }
        }

        cur = (cur + 1) & (GSTAGES - 1);
        nxt = (nxt + 1) & (GSTAGES - 1);
    }
}

// ---------------------------------------------------------------------------
// Fused Q + KV projection: grid = 1024 KV CTAs then 128 Q CTAs.
// ---------------------------------------------------------------------------
__global__ void __launch_bounds__(256) proj_fused_kernel(
    const __nv_bfloat16* __restrict__ qnh, const __nv_bfloat16* __restrict__ cnh,
    const __nv_bfloat16* __restrict__ wqh, const __nv_bfloat16* __restrict__ wkvh,
    const float* __restrict__ bq, const float* __restrict__ bk,
    const float* __restrict__ bv,
    __nv_bfloat16* __restrict__ Qp, __nv_bfloat16* __restrict__ Kp,
    __nv_bfloat16* __restrict__ Vp)
{
    extern __shared__ __align__(16) __nv_bfloat16 gsm[];

    GemmCtx cx;
    cx.kofs = 0; cx.nk = DD / 32;
    const float* bias;
    __nv_bfloat16* Co;
    int nbase;
    const int bid = blockIdx.x;
    if (bid < 1024) {
        cx.A = cnh; cx.W = wkvh;
        cx.m0 = (bid >> 4) * 128;
        cx.n0 = (bid & 15) * 128;
        if (cx.n0 < DD) { bias = bk; Co = Kp; nbase = cx.n0; }
        else            { bias = bv; Co = Vp; nbase = cx.n0 - DD; }
    } else {
        const int i2 = bid - 1024;
        cx.A = qnh; cx.W = wqh;
        cx.m0 = (i2 >> 3) * 128;
        cx.n0 = (i2 & 7) * 128;
        bias = bq; Co = Qp; nbase = cx.n0;
    }

    float acc[2][8][4];
    gemm_mainloop(cx, gsm, acc);

    const int t = threadIdx.x, lane = t & 31, w = t >> 5;
    const int wm = w >> 1, wn = w & 1, g = lane >> 2, tg = lane & 3;

    #pragma unroll
    for (int mf = 0; mf < 2; mf++) {
        #pragma unroll
        for (int nf = 0; nf < 8; nf++) {
            const int col = nbase + wn * 64 + nf * 8 + tg * 2;
            const float bx = bias[col], by = bias[col + 1];
            #pragma unroll
            for (int half = 0; half < 2; half++) {
                const size_t grow = (size_t)(cx.m0 + wm * 32 + mf * 16 + g + half * 8);
                *reinterpret_cast<__nv_bfloat162*>(Co + grow * DD + col) =
                    __floats2bfloat162_rn(acc[mf][nf][half * 2 + 0] + bx,
                                          acc[mf][nf][half * 2 + 1] + by);
            }
        }
    }
}

// ---------------------------------------------------------------------------
// Split-K O projection: grid (8, 16, 2); z selects K half. Writes raw fp32
// partials (no bias/residual) to Op[z].
// ---------------------------------------------------------------------------
__global__ void __launch_bounds__(256) oproj_split_kernel(
    const __nv_bfloat16* __restrict__ A, const __nv_bfloat16* __restrict__ W,
    float* __restrict__ Op)
{
    extern __shared__ __align__(16) __nv_bfloat16 gsm[];

    const int sp = blockIdx.z;
    GemmCtx cx;
    cx.A = A; cx.W = W;
    cx.m0 = blockIdx.y * 128;
    cx.n0 = blockIdx.x * 128;
    cx.kofs = sp * (DD / 2);
    cx.nk = DD / 64;   // 16 iterations of k32

    float acc[2][8][4];
    gemm_mainloop(cx, gsm, acc);

    float* Ops = Op + (size_t)sp * MQ * DD;
    const int t = threadIdx.x, lane = t & 31, w = t >> 5;
    const int wm = w >> 1, wn = w & 1, g = lane >> 2, tg = lane & 3;

    #pragma unroll
    for (int mf = 0; mf < 2; mf++) {
        #pragma unroll
        for (int nf = 0; nf < 8; nf++) {
            const int col = cx.n0 + wn * 64 + nf * 8 + tg * 2;
            #pragma unroll
            for (int half = 0; half < 2; half++) {
                const size_t grow = (size_t)(cx.m0 + wm * 32 + mf * 16 + g + half * 8);
                float2 o;
                o.x = acc[mf][nf][half * 2 + 0];
                o.y = acc[mf][nf][half * 2 + 1];
                *reinterpret_cast<float2*>(Ops + grow * DD + col) = o;
            }
        }
    }
}

// ---------------------------------------------------------------------------
// Split-K combine: out = p0 + p1 + bias + qn. Grid MQ x 256 threads (4 cols/th).
// ---------------------------------------------------------------------------
__global__ void __launch_bounds__(256) oproj_combine_kernel(
    const float* __restrict__ Op, const float* __restrict__ bias,
    const float* __restrict__ qn, float* __restrict__ out)
{
    const int R = blockIdx.x;
    const int col = threadIdx.x * 4;

    const float4 p0 = *reinterpret_cast<const float4*>(Op + (size_t)R * DD + col);
    const float4 p1 = *reinterpret_cast<const float4*>(Op + (size_t)MQ * DD + (size_t)R * DD + col);
    const float4 bv = *reinterpret_cast<const float4*>(bias + col);
    const float4 rv = *reinterpret_cast<const float4*>(qn + (size_t)R * DD + col);

    float4 o;
    o.x = p0.x + p1.x + bv.x + rv.x;
    o.y = p0.y + p1.y + bv.y + rv.y;
    o.z = p0.z + p1.z + bv.z + rv.z;
    o.w = p0.w + p1.w + bv.w + rv.w;
    *reinterpret_cast<float4*>(out + (size_t)R * DD + col) = o;
}

// ---------------------------------------------------------------------------
// BF16 flash attention (round-11/15 structure): 128 threads = 4 warps,
// q-tile 128, warp tile m32xn64, K/V frags shared across m-halves (1 wf/MMA),
// Q frags hoisted, P in registers, skip-rescale (exact).
// ---------------------------------------------------------------------------
#define QSTR 72
#define OFF_Q 0
#define OFF_K (128 * QSTR)
#define OFF_V (OFF_K + 2 * 64 * QSTR)
#define SM_ELEMS (OFF_V + 2 * 64 * QSTR)
#define KVBUF (64 * QSTR)
#define SSCALE 0.18033688f   /* 0.125 * log2(e) */

__global__ void __launch_bounds__(128) attn_bf16_kernel(
    const __nv_bfloat16* __restrict__ Q, const __nv_bfloat16* __restrict__ K,
    const __nv_bfloat16* __restrict__ V, __nv_bfloat16* __restrict__ O)
{
    extern __shared__ __align__(16) __nv_bfloat16 smem[];
    const unsigned sm_base = (unsigned)__cvta_generic_to_shared(smem);

    const int b  = blockIdx.z;
    const int h  = blockIdx.y;
    const int q0 = blockIdx.x * 128;
    const int t  = threadIdx.x;
    const int w  = t >> 5;           // 0..3
    const int lane = t & 31;
    const int g  = lane >> 2;
    const int tg = lane & 3;
    const int wrow = w * 32;         // warp's 32 q rows

    const int arow_in  = (lane & 7) + ((lane >> 3) & 1) * 8;
    const int akoff_in = (lane >> 4) * 8;
    const int brow_in  = (lane & 7) + (lane >> 4) * 8;
    const int bkoff_in = ((lane >> 3) & 1) * 8;

    const __nv_bfloat16* Qb = Q + ((size_t)(b * NQ + q0)) * DD + h * HDIM;
    const __nv_bfloat16* Kb = K + ((size_t)(b * NC)) * DD + h * HDIM;
    const __nv_bfloat16* Vb = V + ((size_t)(b * NC)) * DD + h * HDIM;

    // Prologue: Q (group 0), then K/V tile 0 (group 1)
    #pragma unroll
    for (int i = t; i < 128 * 8; i += 128) {
        const int r = i >> 3, c = (i & 7) * 8;
        cp_async16(sm_base + (OFF_Q + r * QSTR + c) * 2, Qb + (size_t)r * DD + c);
    }
    cp_commit();
    #pragma unroll
    for (int i = t; i < 64 * 8; i += 128) {
        const int r = i >> 3, c = (i & 7) * 8;
        cp_async16(sm_base + (OFF_K + r * QSTR + c) * 2, Kb + (size_t)r * DD + c);
        cp_async16(sm_base + (OFF_V + r * QSTR + c) * 2, Vb + (size_t)r * DD + c);
    }
    cp_commit();

    // Q ready (<=1 group pending); hoist Q fragments into registers
    cp_wait<1>();
    __syncthreads();
    unsigned qa[2][4][4];
    #pragma unroll
    for (int mf = 0; mf < 2; mf++)
        #pragma unroll
        for (int ks = 0; ks < 4; ks++)
            ldsm_x4(qa[mf][ks][0], qa[mf][ks][1], qa[mf][ks][2], qa[mf][ks][3],
                    sm_base + (OFF_Q + (wrow + mf * 16 + arow_in) * QSTR
                               + ks * 16 + akoff_in) * 2);

    float m_i[4], l_i[4], of[2][8][4];
    #pragma unroll
    for (int i = 0; i < 4; i++) { m_i[i] = -INFINITY; l_i[i] = 0.f; }
    #pragma unroll
    for (int mf = 0; mf < 2; mf++)
        #pragma unroll
        for (int nf = 0; nf < 8; nf++)
            #pragma unroll
            for (int i = 0; i < 4; i++) of[mf][nf][i] = 0.f;

    const int NT = NC / 64;
    for (int it = 0; it < NT; it++) {
        const int cur = it & 1;
        cp_wait<0>();
        __syncthreads();

        if (it + 1 < NT) {
            const int nxt = cur ^ 1;
            #pragma unroll
            for (int i = t; i < 64 * 8; i += 128) {
                const int r = i >> 3, c = (i & 7) * 8;
                const size_t grow = (size_t)((it + 1) * 64 + r) * DD + c;
                cp_async16(sm_base + (OFF_K + nxt * KVBUF + r * QSTR + c) * 2, Kb + grow);
                cp_async16(sm_base + (OFF_V + nxt * KVBUF + r * QSTR + c) * 2, Vb + grow);
            }
            cp_commit();
        }

        const int kbase = OFF_K + cur * KVBUF;
        const int vbase = OFF_V + cur * KVBUF;

        // ---- S = Q K^T : warp m32 x n64 over k=64; K frags shared by m-halves
        float sf[2][8][4];
        #pragma unroll
        for (int mf = 0; mf < 2; mf++)
            #pragma unroll
            for (int nf = 0; nf < 8; nf++)
                #pragma unroll
                for (int i = 0; i < 4; i++) sf[mf][nf][i] = 0.f;

        #pragma unroll
        for (int ks = 0; ks < 4; ks++) {
            unsigned bf[4][4];
            #pragma unroll
            for (int ng = 0; ng < 4; ng++) {
                ldsm_x4(bf[ng][0], bf[ng][1], bf[ng][2], bf[ng][3],
                        sm_base + (kbase + (ng * 16 + brow_in) * QSTR
                                   + ks * 16 + bkoff_in) * 2);
            }
            #pragma unroll
            for (int ng = 0; ng < 4; ng++) {
                mma_bf16(sf[0][2*ng+0], qa[0][ks], bf[ng][0], bf[ng][1]);
                mma_bf16(sf[1][2*ng+0], qa[1][ks], bf[ng][0], bf[ng][1]);
                mma_bf16(sf[0][2*ng+1], qa[0][ks], bf[ng][2], bf[ng][3]);
                mma_bf16(sf[1][2*ng+1], qa[1][ks], bf[ng][2], bf[ng][3]);
            }
        }

        // ---- online softmax per m-half; P packed into A-fragments ----
        unsigned pa[2][4][4];
        #pragma unroll
        for (int mf = 0; mf < 2; mf++) {
            float mx0 = -INFINITY, mx1 = -INFINITY;
            #pragma unroll
            for (int nf = 0; nf < 8; nf++) {
                mx0 = fmaxf(mx0, fmaxf(sf[mf][nf][0], sf[mf][nf][1]));
                mx1 = fmaxf(mx1, fmaxf(sf[mf][nf][2], sf[mf][nf][3]));
            }
            mx0 = fmaxf(mx0, __shfl_xor_sync(0xffffffffu, mx0, 1));
            mx0 = fmaxf(mx0, __shfl_xor_sync(0xffffffffu, mx0, 2));
            mx1 = fmaxf(mx1, __shfl_xor_sync(0xffffffffu, mx1, 1));
            mx1 = fmaxf(mx1, __shfl_xor_sync(0xffffffffu, mx1, 2));

            const float mn0 = fmaxf(m_i[mf * 2 + 0], mx0);   // raw units
            const float mn1 = fmaxf(m_i[mf * 2 + 1], mx1);
            const float f0 = exp2f((m_i[mf * 2 + 0] - mn0) * SSCALE);
            const float f1 = exp2f((m_i[mf * 2 + 1] - mn1) * SSCALE);
            const float c0 = mn0 * SSCALE;
            const float c1 = mn1 * SSCALE;

            float s0 = 0.f, s1 = 0.f;
            #pragma unroll
            for (int nf = 0; nf < 8; nf++) {
                const float p0 = exp2f(fmaf(sf[mf][nf][0], SSCALE, -c0));
                const float p1 = exp2f(fmaf(sf[mf][nf][1], SSCALE, -c0));
                const float p2 = exp2f(fmaf(sf[mf][nf][2], SSCALE, -c1));
                const float p3 = exp2f(fmaf(sf[mf][nf][3], SSCALE, -c1));
                s0 += p0 + p1;
                s1 += p2 + p3;
                const int ks = nf >> 1, hf = nf & 1;
                pa[mf][ks][hf * 2 + 0] = pack_bf16x2(p0, p1);   // row g
                pa[mf][ks][hf * 2 + 1] = pack_bf16x2(p2, p3);   // row g+8
            }
            s0 += __shfl_xor_sync(0xffffffffu, s0, 1);
            s0 += __shfl_xor_sync(0xffffffffu, s0, 2);
            s1 += __shfl_xor_sync(0xffffffffu, s1, 1);
            s1 += __shfl_xor_sync(0xffffffffu, s1, 2);

            l_i[mf * 2 + 0] = l_i[mf * 2 + 0] * f0 + s0;
            l_i[mf * 2 + 1] = l_i[mf * 2 + 1] * f1 + s1;
            m_i[mf * 2 + 0] = mn0;
            m_i[mf * 2 + 1] = mn1;

            // skip-rescale: exact when the running max is unchanged in all rows
            const bool resc = !__all_sync(0xffffffffu, (f0 == 1.f) && (f1 == 1.f));
            if (resc) {
                #pragma unroll
                for (int nf = 0; nf < 8; nf++) {
                    of[mf][nf][0] *= f0; of[mf][nf][1] *= f0;
                    of[mf][nf][2] *= f1; of[mf][nf][3] *= f1;
                }
            }
        }

        // ---- O += P V : V frags shared by both m-halves ----
        #pragma unroll
        for (int ks = 0; ks < 4; ks++) {
            unsigned bf[4][4];
            #pragma unroll
            for (int ng = 0; ng < 4; ng++) {
                ldsm_x4_trans(bf[ng][0], bf[ng][1], bf[ng][2], bf[ng][3],
                              sm_base + (vbase + (ks * 16 + arow_in) * QSTR
                                         + ng * 16 + akoff_in) * 2);
            }
            #pragma unroll
            for (int ng = 0; ng < 4; ng++) {
                mma_bf16(of[0][2*ng+0], pa[0][ks], bf[ng][0], bf[ng][1]);
                mma_bf16(of[1][2*ng+0], pa[1][ks], bf[ng][0], bf[ng][1]);
                mma_bf16(of[0][2*ng+1], pa[0][ks], bf[ng][2], bf[ng][3]);
                mma_bf16(of[1][2*ng+1], pa[1][ks], bf[ng][2], bf[ng][3]);
            }
        }
    }

    // Epilogue
    __nv_bfloat16* Ob = O + ((size_t)(b * NQ + q0)) * DD + h * HDIM;
    #pragma unroll
    for (int mf = 0; mf < 2; mf++) {
        const float inv0 = 1.f / l_i[mf * 2 + 0];
        const float inv1 = 1.f / l_i[mf * 2 + 1];
        #pragma unroll
        for (int nf = 0; nf < 8; nf++) {
            const int col = nf * 8 + tg * 2;
            const int r0 = wrow + mf * 16 + g;
            *reinterpret_cast<__nv_bfloat162*>(Ob + (size_t)r0 * DD + col) =
                __floats2bfloat162_rn(of[mf][nf][0] * inv0, of[mf][nf][1] * inv0);
            *reinterpret_cast<__nv_bfloat162*>(Ob + (size_t)(r0 + 8) * DD + col) =
                __floats2bfloat162_rn(of[mf][nf][2] * inv1, of[mf][nf][3] * inv1);
        }
    }
}

// ---------------------------------------------------------------------------
// Launcher
// ---------------------------------------------------------------------------
extern "C" void kernel_launch(void* const* d_in, const int* in_sizes, int n_in,
                              void* d_out, int out_size)
{
    const float* query   = (const float*)d_in[0];
    const float* context = (const float*)d_in[1];
    const float* wq = (const float*)d_in[2];
    const float* bq = (const float*)d_in[3];
    const float* wk = (const float*)d_in[4];
    const float* bk = (const float*)d_in[5];
    const float* wv = (const float*)d_in[6];
    const float* bv = (const float*)d_in[7];
    const float* wo = (const float*)d_in[8];
    const float* bo = (const float*)d_in[9];
    const float* g_q  = (const float*)d_in[10];
    const float* b_q  = (const float*)d_in[11];
    const float* g_kv = (const float*)d_in[12];
    const float* b_kv = (const float*)d_in[13];
    float* out = (float*)d_out;

    void *qn_, *qnh_, *cnh_, *qp_, *kp_, *vp_, *ao_, *wqh_, *wkvh_, *woh_, *op_;
    cudaGetSymbolAddress(&qn_,   g_qn);
    cudaGetSymbolAddress(&qnh_,  g_qnh);
    cudaGetSymbolAddress(&cnh_,  g_cnh);
    cudaGetSymbolAddress(&qp_,   g_Qp);
    cudaGetSymbolAddress(&kp_,   g_Kp);
    cudaGetSymbolAddress(&vp_,   g_Vp);
    cudaGetSymbolAddress(&ao_,   g_AO);
    cudaGetSymbolAddress(&wqh_,  g_wqh);
    cudaGetSymbolAddress(&wkvh_, g_wkvh);
    cudaGetSymbolAddress(&woh_,  g_woh);
    cudaGetSymbolAddress(&op_,   g_Op);
    float* qn = (float*)qn_;
    __nv_bfloat16* qnh  = (__nv_bfloat16*)qnh_;
    __nv_bfloat16* cnh  = (__nv_bfloat16*)cnh_;
    __nv_bfloat16* Qp   = (__nv_bfloat16*)qp_;
    __nv_bfloat16* Kp   = (__nv_bfloat16*)kp_;
    __nv_bfloat16* Vp   = (__nv_bfloat16*)vp_;
    __nv_bfloat16* AO   = (__nv_bfloat16*)ao_;
    __nv_bfloat16* wqh  = (__nv_bfloat16*)wqh_;
    __nv_bfloat16* wkvh = (__nv_bfloat16*)wkvh_;
    __nv_bfloat16* woh  = (__nv_bfloat16*)woh_;
    float* Op = (float*)op_;

    const int attn_smem = SM_ELEMS * 2;      // 55296 bytes
    static int configured = 0;
    if (!configured) {
        cudaFuncSetAttribute(attn_bf16_kernel,
                             cudaFuncAttributeMaxDynamicSharedMemorySize, attn_smem);
        cudaFuncSetAttribute(proj_fused_kernel,
                             cudaFuncAttributeMaxDynamicSharedMemorySize, GEMM_SMEM);
        cudaFuncSetAttribute(oproj_split_kernel,
                             cudaFuncAttributeMaxDynamicSharedMemorySize, GEMM_SMEM);
        configured = 1;
    }

    // 1. Warp-per-row LayerNorms + weight convert
    ln_cvt_kernel<<<LN_BLOCKS + 4096, 256>>>(query, context, g_q, b_q, g_kv, b_kv,
                                             qn, qnh, cnh,
                                             wq, wk, wv, wo, wqh, wkvh, woh);

    // 2. Fused Q + KV projections
    proj_fused_kernel<<<1152, 256, GEMM_SMEM>>>(qnh, cnh, wqh, wkvh,
                                                bq, bk, bv, Qp, Kp, Vp);

    // 3. Flash attention (round-15 best structure)
    dim3 ga(NQ / 128, NH, BB);          // (8, 16, 2)
    attn_bf16_kernel<<<ga, 128, attn_smem>>>(Qp, Kp, Vp, AO);

    // 4. Split-K output projection + combine (bias + residual)
    dim3 go(DD / 128, MQ / 128, 2);     // (8, 16, 2) = 256 CTAs
    oproj_split_kernel<<<go, 256, GEMM_SMEM>>>(AO, woh, Op);
    oproj_combine_kernel<<<MQ, 256>>>(Op, bo, qn, out);
}